// round 4
// baseline (speedup 1.0000x reference)
#include <cuda_runtime.h>
#include <cstdint>

#define B_ 4
#define L_ 2048
#define D_ 1024
#define H_ 16

// Scratch (device globals; allocation-free per harness rules)
__device__ float g_qkv[B_ * L_ * 3 * D_];   // [B*L, 3072], tf32-rounded
__device__ float g_attn[B_ * L_ * D_];      // [B*L, 1024], tf32-rounded
__device__ float g_xr[B_ * L_ * D_];        // x rounded
__device__ float g_wq[3 * D_ * D_];         // w_qkv rounded
__device__ float g_wp[D_ * D_];             // w_proj rounded

// ---------------- helpers ----------------
__device__ __forceinline__ float rna(float x) {
    uint32_t u; asm("cvt.rna.tf32.f32 %0, %1;" : "=r"(u) : "f"(x));
    return __uint_as_float(u);
}
__device__ __forceinline__ float ex2f(float x) {
    float r; asm("ex2.approx.ftz.f32 %0, %1;" : "=f"(r) : "f"(x)); return r;
}
__device__ __forceinline__ void mma8(float* c, const float* a, float b0, float b1) {
    asm volatile(
        "mma.sync.aligned.m16n8k8.row.col.f32.tf32.tf32.f32 "
        "{%0,%1,%2,%3}, {%4,%5,%6,%7}, {%8,%9}, {%0,%1,%2,%3};"
        : "+f"(c[0]), "+f"(c[1]), "+f"(c[2]), "+f"(c[3])
        : "r"(__float_as_uint(a[0])), "r"(__float_as_uint(a[1])),
          "r"(__float_as_uint(a[2])), "r"(__float_as_uint(a[3])),
          "r"(__float_as_uint(b0)), "r"(__float_as_uint(b1)));
}
__device__ __forceinline__ uint32_t sptr(const void* p) {
    uint32_t a;
    asm("{ .reg .u64 t; cvta.to.shared.u64 t, %1; cvt.u32.u64 %0, t; }" : "=r"(a) : "l"(p));
    return a;
}
__device__ __forceinline__ void cp16(uint32_t s, const void* g) {
    asm volatile("cp.async.cg.shared.global [%0], [%1], 16;" :: "r"(s), "l"(g));
}
#define CPC() asm volatile("cp.async.commit_group;" ::: "memory")
#define CPW(n) asm volatile("cp.async.wait_group %0;" :: "n"(n) : "memory")

// ---------------------------------------------------------------------------
// tf32 rounding pre-pass (float4 grid-stride)
// ---------------------------------------------------------------------------
__global__ void round_pass(const float* __restrict__ in, float* __restrict__ out, int n4)
{
    int i = blockIdx.x * blockDim.x + threadIdx.x;
    int stride = gridDim.x * blockDim.x;
    for (; i < n4; i += stride) {
        float4 v = ((const float4*)in)[i];
        v.x = rna(v.x); v.y = rna(v.y); v.z = rna(v.z); v.w = rna(v.w);
        ((float4*)out)[i] = v;
    }
}

// ---------------------------------------------------------------------------
// Tensor-core GEMM (NT): C[m,n] = sum_k A[m,k]*Bm[n,k]; inputs pre-rounded.
// Block tile 256x128, 256 threads (8 warps, warp tile 64x64), k-tile 32,
// cp.async double buffer. No CVTs in the hot loop.
// ---------------------------------------------------------------------------
#define GP 36
#define GEMM_SMEM ((2 * 256 * GP + 2 * 128 * GP) * 4)

__global__ __launch_bounds__(256, 1)
void gemm_tc(const float* __restrict__ A, const float* __restrict__ Bm,
             float* __restrict__ C, int M, int N, int K, int roundOut)
{
    extern __shared__ float sm[];
    float* Asm = sm;                  // [2][256][GP]
    float* Bsm = sm + 2 * 256 * GP;   // [2][128][GP]

    const int tid = threadIdx.x, warp = tid >> 5, lane = tid & 31;
    const int g = lane >> 2, tg = lane & 3;
    const int wm0 = (warp >> 1) * 64, wn0 = (warp & 1) * 64;
    const size_t ar0 = (size_t)blockIdx.y * 256, br0 = (size_t)blockIdx.x * 128;

    float acc[4][8][4];
#pragma unroll
    for (int mi = 0; mi < 4; mi++)
#pragma unroll
        for (int ni = 0; ni < 8; ni++)
#pragma unroll
            for (int r = 0; r < 4; r++) acc[mi][ni][r] = 0.f;

    auto stage = [&](int s, int k0) {
        float* Ab = Asm + s * 256 * GP;
        float* Bb = Bsm + s * 128 * GP;
#pragma unroll
        for (int i = 0; i < 8; i++) {
            int v = tid + i * 256, row = v >> 3, c = (v & 7) * 4;
            cp16(sptr(Ab + row * GP + c), A + (ar0 + row) * (size_t)K + k0 + c);
        }
#pragma unroll
        for (int i = 0; i < 4; i++) {
            int v = tid + i * 256, row = v >> 3, c = (v & 7) * 4;
            cp16(sptr(Bb + row * GP + c), Bm + (br0 + row) * (size_t)K + k0 + c);
        }
    };

    const int nk = K >> 5;   // k-tile 32
    stage(0, 0); CPC();

    for (int kt = 0; kt < nk; kt++) {
        CPW(0); __syncthreads();
        if (kt + 1 < nk) { stage((kt + 1) & 1, (kt + 1) * 32); CPC(); }
        const float* Ab = Asm + (kt & 1) * 256 * GP;
        const float* Bb = Bsm + (kt & 1) * 128 * GP;
#pragma unroll
        for (int ks = 0; ks < 4; ks++) {
            const int k0 = ks * 8;
            float a[4][4];
#pragma unroll
            for (int mi = 0; mi < 4; mi++) {
                const float* ap = Ab + (wm0 + mi * 16) * GP + k0;
                a[mi][0] = ap[g * GP + tg];
                a[mi][1] = ap[(g + 8) * GP + tg];
                a[mi][2] = ap[g * GP + tg + 4];
                a[mi][3] = ap[(g + 8) * GP + tg + 4];
            }
#pragma unroll
            for (int ni = 0; ni < 8; ni++) {
                const float* bp = Bb + (wn0 + ni * 8 + g) * GP + k0;
                float b0 = bp[tg], b1 = bp[tg + 4];
#pragma unroll
                for (int mi = 0; mi < 4; mi++) mma8(acc[mi][ni], a[mi], b0, b1);
            }
        }
        __syncthreads();
    }

#pragma unroll
    for (int mi = 0; mi < 4; mi++) {
#pragma unroll
        for (int ni = 0; ni < 8; ni++) {
            size_t col = br0 + wn0 + ni * 8 + 2 * tg;
            float v0 = acc[mi][ni][0], v1 = acc[mi][ni][1];
            float v2 = acc[mi][ni][2], v3 = acc[mi][ni][3];
            if (roundOut) { v0 = rna(v0); v1 = rna(v1); v2 = rna(v2); v3 = rna(v3); }
            *(float2*)&C[(ar0 + wm0 + mi * 16 + g) * (size_t)N + col] = make_float2(v0, v1);
            *(float2*)&C[(ar0 + wm0 + mi * 16 + g + 8) * (size_t)N + col] = make_float2(v2, v3);
        }
    }
}

// ---------------------------------------------------------------------------
// Tensor-core flash attention (proven R3 structure). Block = 128 queries x
// (b,h). 8 warps x 16 query rows. Key tiles of 64, cp.async double buffered.
// Output rna-rounded so proj GEMM consumes tf32-ready data.
// ---------------------------------------------------------------------------
#define QS 76
#define VS 72
#define ATTN_SMEM ((128*QS + 2*64*QS + 2*64*VS + 128*QS) * 4)

__global__ __launch_bounds__(256)
void attn_tc(const float* __restrict__ qkv, float* __restrict__ out)
{
    extern __shared__ float smf[];
    float* Qs  = smf;                  // [128][76]
    float* Ksm = Qs + 128 * QS;        // [2][64][76]
    float* Vsm = Ksm + 2 * 64 * QS;    // [2][64][72]
    float* Ps  = Vsm + 2 * 64 * VS;    // [128][76]

    const int tid = threadIdx.x, warp = tid >> 5, lane = tid & 31;
    const int g = lane >> 2, tg = lane & 3;
    const int rm = warp * 16;
    const int q0 = blockIdx.x * 128, h = blockIdx.y, b = blockIdx.z;
    const float c2s = 0.18033688f;  // 0.125 * log2(e)

#pragma unroll
    for (int i = 0; i < 8; i++) {
        int v = tid + i * 256, row = v >> 4, c = (v & 15) * 4;
        *(float4*)&Qs[row * QS + c] =
            *(const float4*)(qkv + ((size_t)(b * L_ + q0 + row)) * 3072 + h * 64 + c);
    }

    auto stage = [&](int s, int kt) {
        const float* base = qkv + ((size_t)(b * L_ + kt * 64)) * 3072 + h * 64;
#pragma unroll
        for (int i = 0; i < 4; i++) {
            int v = tid + i * 256, row = v >> 4, c = (v & 15) * 4;
            cp16(sptr(&Ksm[(s * 64 + row) * QS + c]), base + (size_t)row * 3072 + 1024 + c);
            cp16(sptr(&Vsm[(s * 64 + row) * VS + c]), base + (size_t)row * 3072 + 2048 + c);
        }
    };
    stage(0, 0); CPC();
    __syncthreads();

    float qa[8][4];
#pragma unroll
    for (int kj = 0; kj < 8; kj++) {
        int k0 = kj * 8;
        qa[kj][0] = Qs[(rm + g) * QS + k0 + tg];
        qa[kj][1] = Qs[(rm + g + 8) * QS + k0 + tg];
        qa[kj][2] = Qs[(rm + g) * QS + k0 + tg + 4];
        qa[kj][3] = Qs[(rm + g + 8) * QS + k0 + tg + 4];
    }

    float m0 = -1e30f, m1 = -1e30f, l0 = 0.f, l1 = 0.f;
    float o[8][4];
#pragma unroll
    for (int ni = 0; ni < 8; ni++)
#pragma unroll
        for (int r = 0; r < 4; r++) o[ni][r] = 0.f;

    for (int kt = 0; kt < 32; kt++) {
        CPW(0); __syncthreads();
        if (kt + 1 < 32) { stage((kt + 1) & 1, kt + 1); CPC(); }
        const float* Kb = &Ksm[(kt & 1) * 64 * QS];
        const float* Vb = &Vsm[(kt & 1) * 64 * VS];

        float s[8][4];
#pragma unroll
        for (int ni = 0; ni < 8; ni++)
#pragma unroll
            for (int r = 0; r < 4; r++) s[ni][r] = 0.f;
#pragma unroll
        for (int kj = 0; kj < 8; kj++) {
            int k0 = kj * 8;
#pragma unroll
            for (int ni = 0; ni < 8; ni++) {
                float b0 = Kb[(ni * 8 + g) * QS + k0 + tg];
                float b1 = Kb[(ni * 8 + g) * QS + k0 + tg + 4];
                mma8(s[ni], qa[kj], b0, b1);
            }
        }

        float mx0 = -1e30f, mx1 = -1e30f;
#pragma unroll
        for (int ni = 0; ni < 8; ni++) {
            mx0 = fmaxf(mx0, fmaxf(s[ni][0], s[ni][1]));
            mx1 = fmaxf(mx1, fmaxf(s[ni][2], s[ni][3]));
        }
        mx0 = fmaxf(mx0, __shfl_xor_sync(~0u, mx0, 1));
        mx0 = fmaxf(mx0, __shfl_xor_sync(~0u, mx0, 2));
        mx1 = fmaxf(mx1, __shfl_xor_sync(~0u, mx1, 1));
        mx1 = fmaxf(mx1, __shfl_xor_sync(~0u, mx1, 2));
        float nm0 = fmaxf(m0, mx0 * c2s), nm1 = fmaxf(m1, mx1 * c2s);
        float cr0 = ex2f(m0 - nm0), cr1 = ex2f(m1 - nm1);
        m0 = nm0; m1 = nm1;

        float rs0 = 0.f, rs1 = 0.f;
#pragma unroll
        for (int ni = 0; ni < 8; ni++) {
            float p0 = ex2f(fmaf(s[ni][0], c2s, -nm0));
            float p1 = ex2f(fmaf(s[ni][1], c2s, -nm0));
            float p2 = ex2f(fmaf(s[ni][2], c2s, -nm1));
            float p3 = ex2f(fmaf(s[ni][3], c2s, -nm1));
            rs0 += p0 + p1; rs1 += p2 + p3;
            *(float2*)&Ps[(rm + g) * QS + ni * 8 + 2 * tg] = make_float2(rna(p0), rna(p1));
            *(float2*)&Ps[(rm + g + 8) * QS + ni * 8 + 2 * tg] = make_float2(rna(p2), rna(p3));
        }
        rs0 += __shfl_xor_sync(~0u, rs0, 1); rs0 += __shfl_xor_sync(~0u, rs0, 2);
        rs1 += __shfl_xor_sync(~0u, rs1, 1); rs1 += __shfl_xor_sync(~0u, rs1, 2);
        l0 = l0 * cr0 + rs0; l1 = l1 * cr1 + rs1;
#pragma unroll
        for (int ni = 0; ni < 8; ni++) {
            o[ni][0] *= cr0; o[ni][1] *= cr0; o[ni][2] *= cr1; o[ni][3] *= cr1;
        }
        __syncwarp();

#pragma unroll
        for (int kj = 0; kj < 8; kj++) {
            int k0 = kj * 8;
            float pa[4];
            pa[0] = Ps[(rm + g) * QS + k0 + tg];
            pa[1] = Ps[(rm + g + 8) * QS + k0 + tg];
            pa[2] = Ps[(rm + g) * QS + k0 + tg + 4];
            pa[3] = Ps[(rm + g + 8) * QS + k0 + tg + 4];
#pragma unroll
            for (int ni = 0; ni < 8; ni++) {
                float b0 = Vb[(k0 + tg) * VS + ni * 8 + g];
                float b1 = Vb[(k0 + tg + 4) * VS + ni * 8 + g];
                mma8(o[ni], pa, b0, b1);
            }
        }
        __syncwarp();
    }

    float li0 = 1.f / l0, li1 = 1.f / l1;
#pragma unroll
    for (int ni = 0; ni < 8; ni++) {
        size_t c = (size_t)h * 64 + ni * 8 + 2 * tg;
        *(float2*)&out[((size_t)(b * L_ + q0 + rm + g)) * 1024 + c] =
            make_float2(rna(o[ni][0] * li0), rna(o[ni][1] * li0));
        *(float2*)&out[((size_t)(b * L_ + q0 + rm + g + 8)) * 1024 + c] =
            make_float2(rna(o[ni][2] * li1), rna(o[ni][3] * li1));
    }
}

// ---------------------------------------------------------------------------
extern "C" void kernel_launch(void* const* d_in, const int* in_sizes, int n_in,
                              void* d_out, int out_size)
{
    (void)in_sizes; (void)n_in; (void)out_size;
    const float* x      = (const float*)d_in[0];
    const float* w_qkv  = (const float*)d_in[1];
    const float* w_proj = (const float*)d_in[2];
    float* out = (float*)d_out;

    float *qkvp, *attnp, *xr, *wq, *wp;
    cudaGetSymbolAddress((void**)&qkvp, g_qkv);
    cudaGetSymbolAddress((void**)&attnp, g_attn);
    cudaGetSymbolAddress((void**)&xr, g_xr);
    cudaGetSymbolAddress((void**)&wq, g_wq);
    cudaGetSymbolAddress((void**)&wp, g_wp);

    const int M = B_ * L_;  // 8192

    // 0) tf32 rounding pre-passes
    round_pass<<<256, 256>>>(x, xr, B_ * L_ * D_ / 4);
    round_pass<<<256, 256>>>(w_qkv, wq, 3 * D_ * D_ / 4);
    round_pass<<<64, 256>>>(w_proj, wp, D_ * D_ / 4);

    // 1) QKV GEMM (rounded epilogue)
    cudaFuncSetAttribute(gemm_tc, cudaFuncAttributeMaxDynamicSharedMemorySize, GEMM_SMEM);
    gemm_tc<<<dim3(3 * D_ / 128, M / 256), 256, GEMM_SMEM>>>(xr, wq, qkvp, M, 3 * D_, D_, 1);

    // 2) Flash attention (rounded epilogue)
    cudaFuncSetAttribute(attn_tc, cudaFuncAttributeMaxDynamicSharedMemorySize, ATTN_SMEM);
    attn_tc<<<dim3(L_ / 128, H_, B_), 256, ATTN_SMEM>>>(qkvp, attnp);

    // 3) Output projection (full fp32 output)
    gemm_tc<<<dim3(D_ / 128, M / 256), 256, GEMM_SMEM>>>(attnp, wp, out, M, D_, D_, 0);
}

// round 7
// speedup vs baseline: 1.6025x; 1.6025x over previous
#include <cuda_runtime.h>
#include <cstdint>

#define B_ 4
#define L_ 2048
#define D_ 1024
#define H_ 16

// Scratch (device globals; allocation-free per harness rules)
__device__ float g_qkv[B_ * L_ * 3 * D_];   // [B*L, 3072], tf32-rounded
__device__ float g_attn[B_ * L_ * D_];      // [B*L, 1024], tf32-rounded
__device__ float g_xr[B_ * L_ * D_];        // x rounded
__device__ float g_wq[3 * D_ * D_];         // w_qkv rounded
__device__ float g_wp[D_ * D_];             // w_proj rounded

// ---------------- helpers ----------------
__device__ __forceinline__ float rna(float x) {
    uint32_t u; asm("cvt.rna.tf32.f32 %0, %1;" : "=r"(u) : "f"(x));
    return __uint_as_float(u);
}
__device__ __forceinline__ float ex2f(float x) {
    float r; asm("ex2.approx.ftz.f32 %0, %1;" : "=f"(r) : "f"(x)); return r;
}
__device__ __forceinline__ void mma8(float* c, const float* a, float b0, float b1) {
    asm volatile(
        "mma.sync.aligned.m16n8k8.row.col.f32.tf32.tf32.f32 "
        "{%0,%1,%2,%3}, {%4,%5,%6,%7}, {%8,%9}, {%0,%1,%2,%3};"
        : "+f"(c[0]), "+f"(c[1]), "+f"(c[2]), "+f"(c[3])
        : "r"(__float_as_uint(a[0])), "r"(__float_as_uint(a[1])),
          "r"(__float_as_uint(a[2])), "r"(__float_as_uint(a[3])),
          "r"(__float_as_uint(b0)), "r"(__float_as_uint(b1)));
}
__device__ __forceinline__ uint32_t sptr(const void* p) {
    uint32_t a;
    asm("{ .reg .u64 t; cvta.to.shared.u64 t, %1; cvt.u32.u64 %0, t; }" : "=r"(a) : "l"(p));
    return a;
}
__device__ __forceinline__ void cp16(uint32_t s, const void* g) {
    asm volatile("cp.async.cg.shared.global [%0], [%1], 16;" :: "r"(s), "l"(g));
}
#define CPC() asm volatile("cp.async.commit_group;" ::: "memory")
#define CPW(n) asm volatile("cp.async.wait_group %0;" :: "n"(n) : "memory")

// ---------------------------------------------------------------------------
// tf32 rounding pre-pass (float4 grid-stride)
// ---------------------------------------------------------------------------
__global__ void round_pass(const float* __restrict__ in, float* __restrict__ out, int n4)
{
    int i = blockIdx.x * blockDim.x + threadIdx.x;
    int stride = gridDim.x * blockDim.x;
    for (; i < n4; i += stride) {
        float4 v = ((const float4*)in)[i];
        v.x = rna(v.x); v.y = rna(v.y); v.z = rna(v.z); v.w = rna(v.w);
        ((float4*)out)[i] = v;
    }
}

// ---------------------------------------------------------------------------
// Tensor-core GEMM (NT): C[m,n] = sum_k A[m,k]*Bm[n,k]; inputs pre-rounded.
// Block 128x128, 128 threads (4 warps, warp tile 64x64), k-tile 32,
// cp.async double buffer in dynamic SMEM. No CVTs in the hot loop.
// ---------------------------------------------------------------------------
#define GP 36
#define GEMM_SMEM (2 * 2 * 128 * GP * 4)   // A+B, 2 buffers: 73728 B

__global__ __launch_bounds__(128)
void gemm_tc(const float* __restrict__ A, const float* __restrict__ Bm,
             float* __restrict__ C, int M, int N, int K, int roundOut)
{
    extern __shared__ float sm[];
    float* Asm = sm;                  // [2][128][GP]
    float* Bsm = sm + 2 * 128 * GP;   // [2][128][GP]

    const int tid = threadIdx.x, warp = tid >> 5, lane = tid & 31;
    const int g = lane >> 2, tg = lane & 3;
    const int wm0 = (warp >> 1) * 64, wn0 = (warp & 1) * 64;
    const size_t ar0 = (size_t)blockIdx.y * 128, br0 = (size_t)blockIdx.x * 128;

    float acc[4][8][4];
#pragma unroll
    for (int mi = 0; mi < 4; mi++)
#pragma unroll
        for (int ni = 0; ni < 8; ni++)
#pragma unroll
            for (int r = 0; r < 4; r++) acc[mi][ni][r] = 0.f;

    auto stage = [&](int s, int k0) {
        float* Ab = Asm + s * 128 * GP;
        float* Bb = Bsm + s * 128 * GP;
#pragma unroll
        for (int i = 0; i < 8; i++) {
            int v = tid + i * 128, row = v >> 3, c = (v & 7) * 4;
            cp16(sptr(Ab + row * GP + c), A + (ar0 + row) * (size_t)K + k0 + c);
        }
#pragma unroll
        for (int i = 0; i < 8; i++) {
            int v = tid + i * 128, row = v >> 3, c = (v & 7) * 4;
            cp16(sptr(Bb + row * GP + c), Bm + (br0 + row) * (size_t)K + k0 + c);
        }
    };

    const int nk = K >> 5;   // k-tile 32
    stage(0, 0); CPC();

    for (int kt = 0; kt < nk; kt++) {
        CPW(0); __syncthreads();
        if (kt + 1 < nk) { stage((kt + 1) & 1, (kt + 1) * 32); CPC(); }
        const float* Ab = Asm + (kt & 1) * 128 * GP;
        const float* Bb = Bsm + (kt & 1) * 128 * GP;
#pragma unroll
        for (int ks = 0; ks < 4; ks++) {
            const int k0 = ks * 8;
            float a[4][4];
#pragma unroll
            for (int mi = 0; mi < 4; mi++) {
                const float* ap = Ab + (wm0 + mi * 16) * GP + k0;
                a[mi][0] = ap[g * GP + tg];
                a[mi][1] = ap[(g + 8) * GP + tg];
                a[mi][2] = ap[g * GP + tg + 4];
                a[mi][3] = ap[(g + 8) * GP + tg + 4];
            }
#pragma unroll
            for (int ni = 0; ni < 8; ni++) {
                const float* bp = Bb + (wn0 + ni * 8 + g) * GP + k0;
                float b0 = bp[tg], b1 = bp[tg + 4];
#pragma unroll
                for (int mi = 0; mi < 4; mi++) mma8(acc[mi][ni], a[mi], b0, b1);
            }
        }
        __syncthreads();
    }

#pragma unroll
    for (int mi = 0; mi < 4; mi++) {
#pragma unroll
        for (int ni = 0; ni < 8; ni++) {
            size_t col = br0 + wn0 + ni * 8 + 2 * tg;
            float v0 = acc[mi][ni][0], v1 = acc[mi][ni][1];
            float v2 = acc[mi][ni][2], v3 = acc[mi][ni][3];
            if (roundOut) { v0 = rna(v0); v1 = rna(v1); v2 = rna(v2); v3 = rna(v3); }
            *(float2*)&C[(ar0 + wm0 + mi * 16 + g) * (size_t)N + col] = make_float2(v0, v1);
            *(float2*)&C[(ar0 + wm0 + mi * 16 + g + 8) * (size_t)N + col] = make_float2(v2, v3);
        }
    }
}

// ---------------------------------------------------------------------------
// Tensor-core flash attention — proven R3/R4 kernel, unchanged.
// Block = 128 queries x (b,h). 8 warps x 16 query rows. Key tiles of 64,
// cp.async double buffered. Output rna-rounded for the proj GEMM.
// ---------------------------------------------------------------------------
#define QS 76
#define VS 72
#define ATTN_SMEM ((128*QS + 2*64*QS + 2*64*VS + 128*QS) * 4)

__global__ __launch_bounds__(256)
void attn_tc(const float* __restrict__ qkv, float* __restrict__ out)
{
    extern __shared__ float smf[];
    float* Qs  = smf;
    float* Ksm = Qs + 128 * QS;
    float* Vsm = Ksm + 2 * 64 * QS;
    float* Ps  = Vsm + 2 * 64 * VS;

    const int tid = threadIdx.x, warp = tid >> 5, lane = tid & 31;
    const int g = lane >> 2, tg = lane & 3;
    const int rm = warp * 16;
    const int q0 = blockIdx.x * 128, h = blockIdx.y, b = blockIdx.z;
    const float c2s = 0.18033688f;  // 0.125 * log2(e)

#pragma unroll
    for (int i = 0; i < 8; i++) {
        int v = tid + i * 256, row = v >> 4, c = (v & 15) * 4;
        *(float4*)&Qs[row * QS + c] =
            *(const float4*)(qkv + ((size_t)(b * L_ + q0 + row)) * 3072 + h * 64 + c);
    }

    auto stage = [&](int s, int kt) {
        const float* base = qkv + ((size_t)(b * L_ + kt * 64)) * 3072 + h * 64;
#pragma unroll
        for (int i = 0; i < 4; i++) {
            int v = tid + i * 256, row = v >> 4, c = (v & 15) * 4;
            cp16(sptr(&Ksm[(s * 64 + row) * QS + c]), base + (size_t)row * 3072 + 1024 + c);
            cp16(sptr(&Vsm[(s * 64 + row) * VS + c]), base + (size_t)row * 3072 + 2048 + c);
        }
    };
    stage(0, 0); CPC();
    __syncthreads();

    float qa[8][4];
#pragma unroll
    for (int kj = 0; kj < 8; kj++) {
        int k0 = kj * 8;
        qa[kj][0] = Qs[(rm + g) * QS + k0 + tg];
        qa[kj][1] = Qs[(rm + g + 8) * QS + k0 + tg];
        qa[kj][2] = Qs[(rm + g) * QS + k0 + tg + 4];
        qa[kj][3] = Qs[(rm + g + 8) * QS + k0 + tg + 4];
    }

    float m0 = -1e30f, m1 = -1e30f, l0 = 0.f, l1 = 0.f;
    float o[8][4];
#pragma unroll
    for (int ni = 0; ni < 8; ni++)
#pragma unroll
        for (int r = 0; r < 4; r++) o[ni][r] = 0.f;

    for (int kt = 0; kt < 32; kt++) {
        CPW(0); __syncthreads();
        if (kt + 1 < 32) { stage((kt + 1) & 1, kt + 1); CPC(); }
        const float* Kb = &Ksm[(kt & 1) * 64 * QS];
        const float* Vb = &Vsm[(kt & 1) * 64 * VS];

        float s[8][4];
#pragma unroll
        for (int ni = 0; ni < 8; ni++)
#pragma unroll
            for (int r = 0; r < 4; r++) s[ni][r] = 0.f;
#pragma unroll
        for (int kj = 0; kj < 8; kj++) {
            int k0 = kj * 8;
#pragma unroll
            for (int ni = 0; ni < 8; ni++) {
                float b0 = Kb[(ni * 8 + g) * QS + k0 + tg];
                float b1 = Kb[(ni * 8 + g) * QS + k0 + tg + 4];
                mma8(s[ni], qa[kj], b0, b1);
            }
        }

        float mx0 = -1e30f, mx1 = -1e30f;
#pragma unroll
        for (int ni = 0; ni < 8; ni++) {
            mx0 = fmaxf(mx0, fmaxf(s[ni][0], s[ni][1]));
            mx1 = fmaxf(mx1, fmaxf(s[ni][2], s[ni][3]));
        }
        mx0 = fmaxf(mx0, __shfl_xor_sync(~0u, mx0, 1));
        mx0 = fmaxf(mx0, __shfl_xor_sync(~0u, mx0, 2));
        mx1 = fmaxf(mx1, __shfl_xor_sync(~0u, mx1, 1));
        mx1 = fmaxf(mx1, __shfl_xor_sync(~0u, mx1, 2));
        float nm0 = fmaxf(m0, mx0 * c2s), nm1 = fmaxf(m1, mx1 * c2s);
        float cr0 = ex2f(m0 - nm0), cr1 = ex2f(m1 - nm1);
        m0 = nm0; m1 = nm1;

        float rs0 = 0.f, rs1 = 0.f;
#pragma unroll
        for (int ni = 0; ni < 8; ni++) {
            float p0 = ex2f(fmaf(s[ni][0], c2s, -nm0));
            float p1 = ex2f(fmaf(s[ni][1], c2s, -nm0));
            float p2 = ex2f(fmaf(s[ni][2], c2s, -nm1));
            float p3 = ex2f(fmaf(s[ni][3], c2s, -nm1));
            rs0 += p0 + p1; rs1 += p2 + p3;
            *(float2*)&Ps[(rm + g) * QS + ni * 8 + 2 * tg] = make_float2(rna(p0), rna(p1));
            *(float2*)&Ps[(rm + g + 8) * QS + ni * 8 + 2 * tg] = make_float2(rna(p2), rna(p3));
        }
        rs0 += __shfl_xor_sync(~0u, rs0, 1); rs0 += __shfl_xor_sync(~0u, rs0, 2);
        rs1 += __shfl_xor_sync(~0u, rs1, 1); rs1 += __shfl_xor_sync(~0u, rs1, 2);
        l0 = l0 * cr0 + rs0; l1 = l1 * cr1 + rs1;
#pragma unroll
        for (int ni = 0; ni < 8; ni++) {
            o[ni][0] *= cr0; o[ni][1] *= cr0; o[ni][2] *= cr1; o[ni][3] *= cr1;
        }
        __syncwarp();

#pragma unroll
        for (int kj = 0; kj < 8; kj++) {
            int k0 = kj * 8;
            float pa[4];
            pa[0] = Ps[(rm + g) * QS + k0 + tg];
            pa[1] = Ps[(rm + g + 8) * QS + k0 + tg];
            pa[2] = Ps[(rm + g) * QS + k0 + tg + 4];
            pa[3] = Ps[(rm + g + 8) * QS + k0 + tg + 4];
#pragma unroll
            for (int ni = 0; ni < 8; ni++) {
                float b0 = Vb[(k0 + tg) * VS + ni * 8 + g];
                float b1 = Vb[(k0 + tg + 4) * VS + ni * 8 + g];
                mma8(o[ni], pa, b0, b1);
            }
        }
        __syncwarp();
    }

    float li0 = 1.f / l0, li1 = 1.f / l1;
#pragma unroll
    for (int ni = 0; ni < 8; ni++) {
        size_t c = (size_t)h * 64 + ni * 8 + 2 * tg;
        *(float2*)&out[((size_t)(b * L_ + q0 + rm + g)) * 1024 + c] =
            make_float2(rna(o[ni][0] * li0), rna(o[ni][1] * li0));
        *(float2*)&out[((size_t)(b * L_ + q0 + rm + g + 8)) * 1024 + c] =
            make_float2(rna(o[ni][2] * li1), rna(o[ni][3] * li1));
    }
}

// ---------------------------------------------------------------------------
extern "C" void kernel_launch(void* const* d_in, const int* in_sizes, int n_in,
                              void* d_out, int out_size)
{
    (void)in_sizes; (void)n_in; (void)out_size;
    const float* x      = (const float*)d_in[0];
    const float* w_qkv  = (const float*)d_in[1];
    const float* w_proj = (const float*)d_in[2];
    float* out = (float*)d_out;

    float *qkvp, *attnp, *xr, *wq, *wp;
    cudaGetSymbolAddress((void**)&qkvp, g_qkv);
    cudaGetSymbolAddress((void**)&attnp, g_attn);
    cudaGetSymbolAddress((void**)&xr, g_xr);
    cudaGetSymbolAddress((void**)&wq, g_wq);
    cudaGetSymbolAddress((void**)&wp, g_wp);

    const int M = B_ * L_;  // 8192

    // 0) tf32 rounding pre-passes
    round_pass<<<256, 256>>>(x, xr, B_ * L_ * D_ / 4);
    round_pass<<<256, 256>>>(w_qkv, wq, 3 * D_ * D_ / 4);
    round_pass<<<64, 256>>>(w_proj, wp, D_ * D_ / 4);

    // 1) QKV GEMM (rounded epilogue)
    cudaFuncSetAttribute(gemm_tc, cudaFuncAttributeMaxDynamicSharedMemorySize, GEMM_SMEM);
    gemm_tc<<<dim3(3 * D_ / 128, M / 128), 128, GEMM_SMEM>>>(xr, wq, qkvp, M, 3 * D_, D_, 1);

    // 2) Flash attention (rounded epilogue)
    cudaFuncSetAttribute(attn_tc, cudaFuncAttributeMaxDynamicSharedMemorySize, ATTN_SMEM);
    attn_tc<<<dim3(L_ / 128, H_, B_), 256, ATTN_SMEM>>>(qkvp, attnp);

    // 3) Output projection (full fp32 output)
    gemm_tc<<<dim3(D_ / 128, M / 128), 128, GEMM_SMEM>>>(attnp, wp, out, M, D_, D_, 0);
}

// round 8
// speedup vs baseline: 1.7038x; 1.0632x over previous
#include <cuda_runtime.h>
#include <cstdint>

#define B_ 4
#define L_ 2048
#define D_ 1024
#define H_ 16

// Scratch (device globals; allocation-free per harness rules)
__device__ float g_qkv[B_ * L_ * 3 * D_];   // [B*L, 3072], tf32-rounded
__device__ float g_attn[B_ * L_ * D_];      // [B*L, 1024], tf32-rounded
__device__ float g_xr[B_ * L_ * D_];        // x rounded
__device__ float g_wq[3 * D_ * D_];         // w_qkv rounded
__device__ float g_wp[D_ * D_];             // w_proj rounded

// ---------------- helpers ----------------
__device__ __forceinline__ float rna(float x) {
    uint32_t u; asm("cvt.rna.tf32.f32 %0, %1;" : "=r"(u) : "f"(x));
    return __uint_as_float(u);
}
__device__ __forceinline__ float ex2f(float x) {
    float r; asm("ex2.approx.ftz.f32 %0, %1;" : "=f"(r) : "f"(x)); return r;
}
__device__ __forceinline__ void mma8(float* c, const float* a, float b0, float b1) {
    asm volatile(
        "mma.sync.aligned.m16n8k8.row.col.f32.tf32.tf32.f32 "
        "{%0,%1,%2,%3}, {%4,%5,%6,%7}, {%8,%9}, {%0,%1,%2,%3};"
        : "+f"(c[0]), "+f"(c[1]), "+f"(c[2]), "+f"(c[3])
        : "r"(__float_as_uint(a[0])), "r"(__float_as_uint(a[1])),
          "r"(__float_as_uint(a[2])), "r"(__float_as_uint(a[3])),
          "r"(__float_as_uint(b0)), "r"(__float_as_uint(b1)));
}
__device__ __forceinline__ uint32_t sptr(const void* p) {
    uint32_t a;
    asm("{ .reg .u64 t; cvta.to.shared.u64 t, %1; cvt.u32.u64 %0, t; }" : "=r"(a) : "l"(p));
    return a;
}
__device__ __forceinline__ void cp16(uint32_t s, const void* g) {
    asm volatile("cp.async.cg.shared.global [%0], [%1], 16;" :: "r"(s), "l"(g));
}
#define CPC() asm volatile("cp.async.commit_group;" ::: "memory")
#define CPW(n) asm volatile("cp.async.wait_group %0;" :: "n"(n) : "memory")

// ---------------------------------------------------------------------------
// tf32 rounding pre-pass (float4 grid-stride)
// ---------------------------------------------------------------------------
__global__ void round_pass(const float* __restrict__ in, float* __restrict__ out, int n4)
{
    int i = blockIdx.x * blockDim.x + threadIdx.x;
    int stride = gridDim.x * blockDim.x;
    for (; i < n4; i += stride) {
        float4 v = ((const float4*)in)[i];
        v.x = rna(v.x); v.y = rna(v.y); v.z = rna(v.z); v.w = rna(v.w);
        ((float4*)out)[i] = v;
    }
}

// ---------------------------------------------------------------------------
// Tensor-core GEMM (NT): C[m,n] = sum_k A[m,k]*Bm[n,k]; inputs pre-rounded.
// Block 128x128, 128 threads (4 warps, warp tile 64x64), k-tile 32,
// cp.async double buffer. Carveout=100 so 2 CTAs/SM are resident.
// ---------------------------------------------------------------------------
#define GP 36
#define GEMM_SMEM (2 * 2 * 128 * GP * 4)   // A+B, 2 buffers: 73728 B

__global__ __launch_bounds__(128)
void gemm_tc(const float* __restrict__ A, const float* __restrict__ Bm,
             float* __restrict__ C, int M, int N, int K, int roundOut)
{
    extern __shared__ float sm[];
    float* Asm = sm;                  // [2][128][GP]
    float* Bsm = sm + 2 * 128 * GP;   // [2][128][GP]

    const int tid = threadIdx.x, warp = tid >> 5, lane = tid & 31;
    const int g = lane >> 2, tg = lane & 3;
    const int wm0 = (warp >> 1) * 64, wn0 = (warp & 1) * 64;
    const size_t ar0 = (size_t)blockIdx.y * 128, br0 = (size_t)blockIdx.x * 128;

    float acc[4][8][4];
#pragma unroll
    for (int mi = 0; mi < 4; mi++)
#pragma unroll
        for (int ni = 0; ni < 8; ni++)
#pragma unroll
            for (int r = 0; r < 4; r++) acc[mi][ni][r] = 0.f;

    auto stage = [&](int s, int k0) {
        float* Ab = Asm + s * 128 * GP;
        float* Bb = Bsm + s * 128 * GP;
#pragma unroll
        for (int i = 0; i < 8; i++) {
            int v = tid + i * 128, row = v >> 3, c = (v & 7) * 4;
            cp16(sptr(Ab + row * GP + c), A + (ar0 + row) * (size_t)K + k0 + c);
        }
#pragma unroll
        for (int i = 0; i < 8; i++) {
            int v = tid + i * 128, row = v >> 3, c = (v & 7) * 4;
            cp16(sptr(Bb + row * GP + c), Bm + (br0 + row) * (size_t)K + k0 + c);
        }
    };

    const int nk = K >> 5;   // k-tile 32
    stage(0, 0); CPC();

    for (int kt = 0; kt < nk; kt++) {
        CPW(0); __syncthreads();
        if (kt + 1 < nk) { stage((kt + 1) & 1, (kt + 1) * 32); CPC(); }
        const float* Ab = Asm + (kt & 1) * 128 * GP;
        const float* Bb = Bsm + (kt & 1) * 128 * GP;
#pragma unroll
        for (int ks = 0; ks < 4; ks++) {
            const int k0 = ks * 8;
            float a[4][4];
#pragma unroll
            for (int mi = 0; mi < 4; mi++) {
                const float* ap = Ab + (wm0 + mi * 16) * GP + k0;
                a[mi][0] = ap[g * GP + tg];
                a[mi][1] = ap[(g + 8) * GP + tg];
                a[mi][2] = ap[g * GP + tg + 4];
                a[mi][3] = ap[(g + 8) * GP + tg + 4];
            }
#pragma unroll
            for (int ni = 0; ni < 8; ni++) {
                const float* bp = Bb + (wn0 + ni * 8 + g) * GP + k0;
                float b0 = bp[tg], b1 = bp[tg + 4];
#pragma unroll
                for (int mi = 0; mi < 4; mi++) mma8(acc[mi][ni], a[mi], b0, b1);
            }
        }
        __syncthreads();
    }

#pragma unroll
    for (int mi = 0; mi < 4; mi++) {
#pragma unroll
        for (int ni = 0; ni < 8; ni++) {
            size_t col = br0 + wn0 + ni * 8 + 2 * tg;
            float v0 = acc[mi][ni][0], v1 = acc[mi][ni][1];
            float v2 = acc[mi][ni][2], v3 = acc[mi][ni][3];
            if (roundOut) { v0 = rna(v0); v1 = rna(v1); v2 = rna(v2); v3 = rna(v3); }
            *(float2*)&C[(ar0 + wm0 + mi * 16 + g) * (size_t)N + col] = make_float2(v0, v1);
            *(float2*)&C[(ar0 + wm0 + mi * 16 + g + 8) * (size_t)N + col] = make_float2(v2, v3);
        }
    }
}

// ---------------------------------------------------------------------------
// Tensor-core flash attention. Block = 128 queries x (b,h). 8 warps x 16
// query rows. Key tiles of 64, cp.async double buffered. P-scratch aliases
// the Q staging buffer (Q lives in registers after the prologue; each warp
// touches only its own 16 rows for both) -> SMEM 112 KB -> 2 CTAs/SM.
// ---------------------------------------------------------------------------
#define QS 76
#define VS 72
#define ATTN_SMEM ((128*QS + 2*64*QS + 2*64*VS) * 4)   // 114688 B

__global__ __launch_bounds__(256, 2)
void attn_tc(const float* __restrict__ qkv, float* __restrict__ out)
{
    extern __shared__ float smf[];
    float* Qs  = smf;                  // [128][76]  (becomes P after prologue)
    float* Ksm = Qs + 128 * QS;        // [2][64][76]
    float* Vsm = Ksm + 2 * 64 * QS;    // [2][64][72]
    float* Ps  = Qs;                   // alias: warp-private rows, no races

    const int tid = threadIdx.x, warp = tid >> 5, lane = tid & 31;
    const int g = lane >> 2, tg = lane & 3;
    const int rm = warp * 16;
    const int q0 = blockIdx.x * 128, h = blockIdx.y, b = blockIdx.z;
    const float c2s = 0.18033688f;  // 0.125 * log2(e)

#pragma unroll
    for (int i = 0; i < 8; i++) {
        int v = tid + i * 256, row = v >> 4, c = (v & 15) * 4;
        *(float4*)&Qs[row * QS + c] =
            *(const float4*)(qkv + ((size_t)(b * L_ + q0 + row)) * 3072 + h * 64 + c);
    }

    auto stage = [&](int s, int kt) {
        const float* base = qkv + ((size_t)(b * L_ + kt * 64)) * 3072 + h * 64;
#pragma unroll
        for (int i = 0; i < 4; i++) {
            int v = tid + i * 256, row = v >> 4, c = (v & 15) * 4;
            cp16(sptr(&Ksm[(s * 64 + row) * QS + c]), base + (size_t)row * 3072 + 1024 + c);
            cp16(sptr(&Vsm[(s * 64 + row) * VS + c]), base + (size_t)row * 3072 + 2048 + c);
        }
    };
    stage(0, 0); CPC();
    __syncthreads();

    // Q fragments -> registers (own rows only); Qs is then reusable as P.
    float qa[8][4];
#pragma unroll
    for (int kj = 0; kj < 8; kj++) {
        int k0 = kj * 8;
        qa[kj][0] = Qs[(rm + g) * QS + k0 + tg];
        qa[kj][1] = Qs[(rm + g + 8) * QS + k0 + tg];
        qa[kj][2] = Qs[(rm + g) * QS + k0 + tg + 4];
        qa[kj][3] = Qs[(rm + g + 8) * QS + k0 + tg + 4];
    }

    float m0 = -1e30f, m1 = -1e30f, l0 = 0.f, l1 = 0.f;
    float o[8][4];
#pragma unroll
    for (int ni = 0; ni < 8; ni++)
#pragma unroll
        for (int r = 0; r < 4; r++) o[ni][r] = 0.f;

    for (int kt = 0; kt < 32; kt++) {
        CPW(0); __syncthreads();
        if (kt + 1 < 32) { stage((kt + 1) & 1, kt + 1); CPC(); }
        const float* Kb = &Ksm[(kt & 1) * 64 * QS];
        const float* Vb = &Vsm[(kt & 1) * 64 * VS];

        float s[8][4];
#pragma unroll
        for (int ni = 0; ni < 8; ni++)
#pragma unroll
            for (int r = 0; r < 4; r++) s[ni][r] = 0.f;
#pragma unroll
        for (int kj = 0; kj < 8; kj++) {
            int k0 = kj * 8;
#pragma unroll
            for (int ni = 0; ni < 8; ni++) {
                float b0 = Kb[(ni * 8 + g) * QS + k0 + tg];
                float b1 = Kb[(ni * 8 + g) * QS + k0 + tg + 4];
                mma8(s[ni], qa[kj], b0, b1);
            }
        }

        float mx0 = -1e30f, mx1 = -1e30f;
#pragma unroll
        for (int ni = 0; ni < 8; ni++) {
            mx0 = fmaxf(mx0, fmaxf(s[ni][0], s[ni][1]));
            mx1 = fmaxf(mx1, fmaxf(s[ni][2], s[ni][3]));
        }
        mx0 = fmaxf(mx0, __shfl_xor_sync(~0u, mx0, 1));
        mx0 = fmaxf(mx0, __shfl_xor_sync(~0u, mx0, 2));
        mx1 = fmaxf(mx1, __shfl_xor_sync(~0u, mx1, 1));
        mx1 = fmaxf(mx1, __shfl_xor_sync(~0u, mx1, 2));
        float nm0 = fmaxf(m0, mx0 * c2s), nm1 = fmaxf(m1, mx1 * c2s);
        float cr0 = ex2f(m0 - nm0), cr1 = ex2f(m1 - nm1);
        m0 = nm0; m1 = nm1;

        float rs0 = 0.f, rs1 = 0.f;
#pragma unroll
        for (int ni = 0; ni < 8; ni++) {
            float p0 = ex2f(fmaf(s[ni][0], c2s, -nm0));
            float p1 = ex2f(fmaf(s[ni][1], c2s, -nm0));
            float p2 = ex2f(fmaf(s[ni][2], c2s, -nm1));
            float p3 = ex2f(fmaf(s[ni][3], c2s, -nm1));
            rs0 += p0 + p1; rs1 += p2 + p3;
            *(float2*)&Ps[(rm + g) * QS + ni * 8 + 2 * tg] = make_float2(rna(p0), rna(p1));
            *(float2*)&Ps[(rm + g + 8) * QS + ni * 8 + 2 * tg] = make_float2(rna(p2), rna(p3));
        }
        rs0 += __shfl_xor_sync(~0u, rs0, 1); rs0 += __shfl_xor_sync(~0u, rs0, 2);
        rs1 += __shfl_xor_sync(~0u, rs1, 1); rs1 += __shfl_xor_sync(~0u, rs1, 2);
        l0 = l0 * cr0 + rs0; l1 = l1 * cr1 + rs1;
#pragma unroll
        for (int ni = 0; ni < 8; ni++) {
            o[ni][0] *= cr0; o[ni][1] *= cr0; o[ni][2] *= cr1; o[ni][3] *= cr1;
        }
        __syncwarp();

#pragma unroll
        for (int kj = 0; kj < 8; kj++) {
            int k0 = kj * 8;
            float pa[4];
            pa[0] = Ps[(rm + g) * QS + k0 + tg];
            pa[1] = Ps[(rm + g + 8) * QS + k0 + tg];
            pa[2] = Ps[(rm + g) * QS + k0 + tg + 4];
            pa[3] = Ps[(rm + g + 8) * QS + k0 + tg + 4];
#pragma unroll
            for (int ni = 0; ni < 8; ni++) {
                float b0 = Vb[(k0 + tg) * VS + ni * 8 + g];
                float b1 = Vb[(k0 + tg + 4) * VS + ni * 8 + g];
                mma8(o[ni], pa, b0, b1);
            }
        }
        __syncwarp();
    }

    float li0 = 1.f / l0, li1 = 1.f / l1;
#pragma unroll
    for (int ni = 0; ni < 8; ni++) {
        size_t c = (size_t)h * 64 + ni * 8 + 2 * tg;
        *(float2*)&out[((size_t)(b * L_ + q0 + rm + g)) * 1024 + c] =
            make_float2(rna(o[ni][0] * li0), rna(o[ni][1] * li0));
        *(float2*)&out[((size_t)(b * L_ + q0 + rm + g + 8)) * 1024 + c] =
            make_float2(rna(o[ni][2] * li1), rna(o[ni][3] * li1));
    }
}

// ---------------------------------------------------------------------------
extern "C" void kernel_launch(void* const* d_in, const int* in_sizes, int n_in,
                              void* d_out, int out_size)
{
    (void)in_sizes; (void)n_in; (void)out_size;
    const float* x      = (const float*)d_in[0];
    const float* w_qkv  = (const float*)d_in[1];
    const float* w_proj = (const float*)d_in[2];
    float* out = (float*)d_out;

    float *qkvp, *attnp, *xr, *wq, *wp;
    cudaGetSymbolAddress((void**)&qkvp, g_qkv);
    cudaGetSymbolAddress((void**)&attnp, g_attn);
    cudaGetSymbolAddress((void**)&xr, g_xr);
    cudaGetSymbolAddress((void**)&wq, g_wq);
    cudaGetSymbolAddress((void**)&wp, g_wp);

    const int M = B_ * L_;  // 8192

    // One-time attribute setup (idempotent, graph-safe)
    cudaFuncSetAttribute(gemm_tc, cudaFuncAttributeMaxDynamicSharedMemorySize, GEMM_SMEM);
    cudaFuncSetAttribute(gemm_tc, cudaFuncAttributePreferredSharedMemoryCarveout, 100);
    cudaFuncSetAttribute(attn_tc, cudaFuncAttributeMaxDynamicSharedMemorySize, ATTN_SMEM);
    cudaFuncSetAttribute(attn_tc, cudaFuncAttributePreferredSharedMemoryCarveout, 100);

    // 0) tf32 rounding pre-passes
    round_pass<<<256, 256>>>(x, xr, B_ * L_ * D_ / 4);
    round_pass<<<256, 256>>>(w_qkv, wq, 3 * D_ * D_ / 4);
    round_pass<<<64, 256>>>(w_proj, wp, D_ * D_ / 4);

    // 1) QKV GEMM (rounded epilogue)
    gemm_tc<<<dim3(3 * D_ / 128, M / 128), 128, GEMM_SMEM>>>(xr, wq, qkvp, M, 3 * D_, D_, 1);

    // 2) Flash attention (rounded epilogue)
    attn_tc<<<dim3(L_ / 128, H_, B_), 256, ATTN_SMEM>>>(qkvp, attnp);

    // 3) Output projection (full fp32 output)
    gemm_tc<<<dim3(D_ / 128, M / 128), 128, GEMM_SMEM>>>(attnp, wp, out, M, D_, D_, 0);
}

// round 9
// speedup vs baseline: 1.7057x; 1.0011x over previous
#include <cuda_runtime.h>
#include <cstdint>

#define B_ 4
#define L_ 2048
#define D_ 1024
#define H_ 16

// Scratch (device globals; allocation-free per harness rules)
__device__ float g_qkv[B_ * L_ * 3 * D_];   // [B*L, 3072], tf32-rounded
__device__ float g_attn[B_ * L_ * D_];      // [B*L, 1024], tf32-rounded
__device__ float g_xr[B_ * L_ * D_];        // x rounded
__device__ float g_wq[3 * D_ * D_];         // w_qkv rounded
__device__ float g_wp[D_ * D_];             // w_proj rounded

// ---------------- helpers ----------------
__device__ __forceinline__ float rna(float x) {
    uint32_t u; asm("cvt.rna.tf32.f32 %0, %1;" : "=r"(u) : "f"(x));
    return __uint_as_float(u);
}
__device__ __forceinline__ float ex2f(float x) {
    float r; asm("ex2.approx.ftz.f32 %0, %1;" : "=f"(r) : "f"(x)); return r;
}
__device__ __forceinline__ void mma8(float* c, const float* a, float b0, float b1) {
    asm volatile(
        "mma.sync.aligned.m16n8k8.row.col.f32.tf32.tf32.f32 "
        "{%0,%1,%2,%3}, {%4,%5,%6,%7}, {%8,%9}, {%0,%1,%2,%3};"
        : "+f"(c[0]), "+f"(c[1]), "+f"(c[2]), "+f"(c[3])
        : "r"(__float_as_uint(a[0])), "r"(__float_as_uint(a[1])),
          "r"(__float_as_uint(a[2])), "r"(__float_as_uint(a[3])),
          "r"(__float_as_uint(b0)), "r"(__float_as_uint(b1)));
}
__device__ __forceinline__ uint32_t sptr(const void* p) {
    uint32_t a;
    asm("{ .reg .u64 t; cvta.to.shared.u64 t, %1; cvt.u32.u64 %0, t; }" : "=r"(a) : "l"(p));
    return a;
}
__device__ __forceinline__ void cp16(uint32_t s, const void* g) {
    asm volatile("cp.async.cg.shared.global [%0], [%1], 16;" :: "r"(s), "l"(g));
}
#define CPC() asm volatile("cp.async.commit_group;" ::: "memory")
#define CPW(n) asm volatile("cp.async.wait_group %0;" :: "n"(n) : "memory")

// ---------------------------------------------------------------------------
// tf32 rounding pre-pass (float4 grid-stride)
// ---------------------------------------------------------------------------
__global__ void round_pass(const float* __restrict__ in, float* __restrict__ out, int n4)
{
    int i = blockIdx.x * blockDim.x + threadIdx.x;
    int stride = gridDim.x * blockDim.x;
    for (; i < n4; i += stride) {
        float4 v = ((const float4*)in)[i];
        v.x = rna(v.x); v.y = rna(v.y); v.z = rna(v.z); v.w = rna(v.w);
        ((float4*)out)[i] = v;
    }
}

// ---------------------------------------------------------------------------
// Tensor-core GEMM (NT): unchanged from R7/R8 (proven 330us @ 2 CTAs/SM).
// Block 128x128, 128 threads (4 warps, warp tile 64x64), k-tile 32,
// cp.async double buffer.
// ---------------------------------------------------------------------------
#define GP 36
#define GEMM_SMEM (2 * 2 * 128 * GP * 4)   // A+B, 2 buffers: 73728 B

__global__ __launch_bounds__(128)
void gemm_tc(const float* __restrict__ A, const float* __restrict__ Bm,
             float* __restrict__ C, int M, int N, int K, int roundOut)
{
    extern __shared__ float sm[];
    float* Asm = sm;                  // [2][128][GP]
    float* Bsm = sm + 2 * 128 * GP;   // [2][128][GP]

    const int tid = threadIdx.x, warp = tid >> 5, lane = tid & 31;
    const int g = lane >> 2, tg = lane & 3;
    const int wm0 = (warp >> 1) * 64, wn0 = (warp & 1) * 64;
    const size_t ar0 = (size_t)blockIdx.y * 128, br0 = (size_t)blockIdx.x * 128;

    float acc[4][8][4];
#pragma unroll
    for (int mi = 0; mi < 4; mi++)
#pragma unroll
        for (int ni = 0; ni < 8; ni++)
#pragma unroll
            for (int r = 0; r < 4; r++) acc[mi][ni][r] = 0.f;

    auto stage = [&](int s, int k0) {
        float* Ab = Asm + s * 128 * GP;
        float* Bb = Bsm + s * 128 * GP;
#pragma unroll
        for (int i = 0; i < 8; i++) {
            int v = tid + i * 128, row = v >> 3, c = (v & 7) * 4;
            cp16(sptr(Ab + row * GP + c), A + (ar0 + row) * (size_t)K + k0 + c);
        }
#pragma unroll
        for (int i = 0; i < 8; i++) {
            int v = tid + i * 128, row = v >> 3, c = (v & 7) * 4;
            cp16(sptr(Bb + row * GP + c), Bm + (br0 + row) * (size_t)K + k0 + c);
        }
    };

    const int nk = K >> 5;   // k-tile 32
    stage(0, 0); CPC();

    for (int kt = 0; kt < nk; kt++) {
        CPW(0); __syncthreads();
        if (kt + 1 < nk) { stage((kt + 1) & 1, (kt + 1) * 32); CPC(); }
        const float* Ab = Asm + (kt & 1) * 128 * GP;
        const float* Bb = Bsm + (kt & 1) * 128 * GP;
#pragma unroll
        for (int ks = 0; ks < 4; ks++) {
            const int k0 = ks * 8;
            float a[4][4];
#pragma unroll
            for (int mi = 0; mi < 4; mi++) {
                const float* ap = Ab + (wm0 + mi * 16) * GP + k0;
                a[mi][0] = ap[g * GP + tg];
                a[mi][1] = ap[(g + 8) * GP + tg];
                a[mi][2] = ap[g * GP + tg + 4];
                a[mi][3] = ap[(g + 8) * GP + tg + 4];
            }
#pragma unroll
            for (int ni = 0; ni < 8; ni++) {
                const float* bp = Bb + (wn0 + ni * 8 + g) * GP + k0;
                float b0 = bp[tg], b1 = bp[tg + 4];
#pragma unroll
                for (int mi = 0; mi < 4; mi++) mma8(acc[mi][ni], a[mi], b0, b1);
            }
        }
        __syncthreads();
    }

#pragma unroll
    for (int mi = 0; mi < 4; mi++) {
#pragma unroll
        for (int ni = 0; ni < 8; ni++) {
            size_t col = br0 + wn0 + ni * 8 + 2 * tg;
            float v0 = acc[mi][ni][0], v1 = acc[mi][ni][1];
            float v2 = acc[mi][ni][2], v3 = acc[mi][ni][3];
            if (roundOut) { v0 = rna(v0); v1 = rna(v1); v2 = rna(v2); v3 = rna(v3); }
            *(float2*)&C[(ar0 + wm0 + mi * 16 + g) * (size_t)N + col] = make_float2(v0, v1);
            *(float2*)&C[(ar0 + wm0 + mi * 16 + g + 8) * (size_t)N + col] = make_float2(v2, v3);
        }
    }
}

// ---------------------------------------------------------------------------
// Tensor-core flash attention. Block = 128 queries x (b,h). 8 warps x 16
// query rows. Key tiles of 64, cp.async double buffered. P aliases Q.
// Pad strides re-derived: 68 == 4 (mod 32) gives conflict-free g*4+tg bank
// pattern for Q/K/P; V stays 72 (tg*8+g). SMEM = 104 KB -> 2 CTAs/SM.
// ---------------------------------------------------------------------------
#define QS 68
#define VS 72
#define ATTN_SMEM ((128*QS + 2*64*QS + 2*64*VS) * 4)   // 106496 B

__global__ __launch_bounds__(256, 2)
void attn_tc(const float* __restrict__ qkv, float* __restrict__ out)
{
    extern __shared__ float smf[];
    float* Qs  = smf;                  // [128][68]  (becomes P after prologue)
    float* Ksm = Qs + 128 * QS;        // [2][64][68]
    float* Vsm = Ksm + 2 * 64 * QS;    // [2][64][72]
    float* Ps  = Qs;                   // alias: warp-private rows, no races

    const int tid = threadIdx.x, warp = tid >> 5, lane = tid & 31;
    const int g = lane >> 2, tg = lane & 3;
    const int rm = warp * 16;
    const int q0 = blockIdx.x * 128, h = blockIdx.y, b = blockIdx.z;
    const float c2s = 0.18033688f;  // 0.125 * log2(e)

#pragma unroll
    for (int i = 0; i < 8; i++) {
        int v = tid + i * 256, row = v >> 4, c = (v & 15) * 4;
        *(float4*)&Qs[row * QS + c] =
            *(const float4*)(qkv + ((size_t)(b * L_ + q0 + row)) * 3072 + h * 64 + c);
    }

    auto stage = [&](int s, int kt) {
        const float* base = qkv + ((size_t)(b * L_ + kt * 64)) * 3072 + h * 64;
#pragma unroll
        for (int i = 0; i < 4; i++) {
            int v = tid + i * 256, row = v >> 4, c = (v & 15) * 4;
            cp16(sptr(&Ksm[(s * 64 + row) * QS + c]), base + (size_t)row * 3072 + 1024 + c);
            cp16(sptr(&Vsm[(s * 64 + row) * VS + c]), base + (size_t)row * 3072 + 2048 + c);
        }
    };
    stage(0, 0); CPC();
    __syncthreads();

    // Q fragments -> registers (own rows only); Qs is then reusable as P.
    float qa[8][4];
#pragma unroll
    for (int kj = 0; kj < 8; kj++) {
        int k0 = kj * 8;
        qa[kj][0] = Qs[(rm + g) * QS + k0 + tg];
        qa[kj][1] = Qs[(rm + g + 8) * QS + k0 + tg];
        qa[kj][2] = Qs[(rm + g) * QS + k0 + tg + 4];
        qa[kj][3] = Qs[(rm + g + 8) * QS + k0 + tg + 4];
    }

    float m0 = -1e30f, m1 = -1e30f, l0 = 0.f, l1 = 0.f;
    float o[8][4];
#pragma unroll
    for (int ni = 0; ni < 8; ni++)
#pragma unroll
        for (int r = 0; r < 4; r++) o[ni][r] = 0.f;

    for (int kt = 0; kt < 32; kt++) {
        CPW(0); __syncthreads();
        if (kt + 1 < 32) { stage((kt + 1) & 1, kt + 1); CPC(); }
        const float* Kb = &Ksm[(kt & 1) * 64 * QS];
        const float* Vb = &Vsm[(kt & 1) * 64 * VS];

        float s[8][4];
#pragma unroll
        for (int ni = 0; ni < 8; ni++)
#pragma unroll
            for (int r = 0; r < 4; r++) s[ni][r] = 0.f;
#pragma unroll
        for (int kj = 0; kj < 8; kj++) {
            int k0 = kj * 8;
#pragma unroll
            for (int ni = 0; ni < 8; ni++) {
                float b0 = Kb[(ni * 8 + g) * QS + k0 + tg];
                float b1 = Kb[(ni * 8 + g) * QS + k0 + tg + 4];
                mma8(s[ni], qa[kj], b0, b1);
            }
        }

        float mx0 = -1e30f, mx1 = -1e30f;
#pragma unroll
        for (int ni = 0; ni < 8; ni++) {
            mx0 = fmaxf(mx0, fmaxf(s[ni][0], s[ni][1]));
            mx1 = fmaxf(mx1, fmaxf(s[ni][2], s[ni][3]));
        }
        mx0 = fmaxf(mx0, __shfl_xor_sync(~0u, mx0, 1));
        mx0 = fmaxf(mx0, __shfl_xor_sync(~0u, mx0, 2));
        mx1 = fmaxf(mx1, __shfl_xor_sync(~0u, mx1, 1));
        mx1 = fmaxf(mx1, __shfl_xor_sync(~0u, mx1, 2));
        float nm0 = fmaxf(m0, mx0 * c2s), nm1 = fmaxf(m1, mx1 * c2s);
        float cr0 = ex2f(m0 - nm0), cr1 = ex2f(m1 - nm1);
        m0 = nm0; m1 = nm1;

        float rs0 = 0.f, rs1 = 0.f;
#pragma unroll
        for (int ni = 0; ni < 8; ni++) {
            float p0 = ex2f(fmaf(s[ni][0], c2s, -nm0));
            float p1 = ex2f(fmaf(s[ni][1], c2s, -nm0));
            float p2 = ex2f(fmaf(s[ni][2], c2s, -nm1));
            float p3 = ex2f(fmaf(s[ni][3], c2s, -nm1));
            rs0 += p0 + p1; rs1 += p2 + p3;
            *(float2*)&Ps[(rm + g) * QS + ni * 8 + 2 * tg] = make_float2(rna(p0), rna(p1));
            *(float2*)&Ps[(rm + g + 8) * QS + ni * 8 + 2 * tg] = make_float2(rna(p2), rna(p3));
        }
        rs0 += __shfl_xor_sync(~0u, rs0, 1); rs0 += __shfl_xor_sync(~0u, rs0, 2);
        rs1 += __shfl_xor_sync(~0u, rs1, 1); rs1 += __shfl_xor_sync(~0u, rs1, 2);
        l0 = l0 * cr0 + rs0; l1 = l1 * cr1 + rs1;
#pragma unroll
        for (int ni = 0; ni < 8; ni++) {
            o[ni][0] *= cr0; o[ni][1] *= cr0; o[ni][2] *= cr1; o[ni][3] *= cr1;
        }
        __syncwarp();

#pragma unroll
        for (int kj = 0; kj < 8; kj++) {
            int k0 = kj * 8;
            float pa[4];
            pa[0] = Ps[(rm + g) * QS + k0 + tg];
            pa[1] = Ps[(rm + g + 8) * QS + k0 + tg];
            pa[2] = Ps[(rm + g) * QS + k0 + tg + 4];
            pa[3] = Ps[(rm + g + 8) * QS + k0 + tg + 4];
#pragma unroll
            for (int ni = 0; ni < 8; ni++) {
                float b0 = Vb[(k0 + tg) * VS + ni * 8 + g];
                float b1 = Vb[(k0 + tg + 4) * VS + ni * 8 + g];
                mma8(o[ni], pa, b0, b1);
            }
        }
        __syncwarp();
    }

    float li0 = 1.f / l0, li1 = 1.f / l1;
#pragma unroll
    for (int ni = 0; ni < 8; ni++) {
        size_t c = (size_t)h * 64 + ni * 8 + 2 * tg;
        *(float2*)&out[((size_t)(b * L_ + q0 + rm + g)) * 1024 + c] =
            make_float2(rna(o[ni][0] * li0), rna(o[ni][1] * li0));
        *(float2*)&out[((size_t)(b * L_ + q0 + rm + g + 8)) * 1024 + c] =
            make_float2(rna(o[ni][2] * li1), rna(o[ni][3] * li1));
    }
}

// ---------------------------------------------------------------------------
extern "C" void kernel_launch(void* const* d_in, const int* in_sizes, int n_in,
                              void* d_out, int out_size)
{
    (void)in_sizes; (void)n_in; (void)out_size;
    const float* x      = (const float*)d_in[0];
    const float* w_qkv  = (const float*)d_in[1];
    const float* w_proj = (const float*)d_in[2];
    float* out = (float*)d_out;

    float *qkvp, *attnp, *xr, *wq, *wp;
    cudaGetSymbolAddress((void**)&qkvp, g_qkv);
    cudaGetSymbolAddress((void**)&attnp, g_attn);
    cudaGetSymbolAddress((void**)&xr, g_xr);
    cudaGetSymbolAddress((void**)&wq, g_wq);
    cudaGetSymbolAddress((void**)&wp, g_wp);

    const int M = B_ * L_;  // 8192

    // One-time attribute setup (idempotent, graph-safe)
    cudaFuncSetAttribute(gemm_tc, cudaFuncAttributeMaxDynamicSharedMemorySize, GEMM_SMEM);
    cudaFuncSetAttribute(gemm_tc, cudaFuncAttributePreferredSharedMemoryCarveout, 100);
    cudaFuncSetAttribute(attn_tc, cudaFuncAttributeMaxDynamicSharedMemorySize, ATTN_SMEM);
    cudaFuncSetAttribute(attn_tc, cudaFuncAttributePreferredSharedMemoryCarveout, 100);

    // 0) tf32 rounding pre-passes
    round_pass<<<256, 256>>>(x, xr, B_ * L_ * D_ / 4);
    round_pass<<<256, 256>>>(w_qkv, wq, 3 * D_ * D_ / 4);
    round_pass<<<64, 256>>>(w_proj, wp, D_ * D_ / 4);

    // 1) QKV GEMM (rounded epilogue)
    gemm_tc<<<dim3(3 * D_ / 128, M / 128), 128, GEMM_SMEM>>>(xr, wq, qkvp, M, 3 * D_, D_, 1);

    // 2) Flash attention (rounded epilogue)
    attn_tc<<<dim3(L_ / 128, H_, B_), 256, ATTN_SMEM>>>(qkvp, attnp);

    // 3) Output projection (full fp32 output)
    gemm_tc<<<dim3(D_ / 128, M / 128), 128, GEMM_SMEM>>>(attnp, wp, out, M, D_, D_, 0);
}